// round 10
// baseline (speedup 1.0000x reference)
#include <cuda_runtime.h>
#include <cstdint>

#define RES   512
#define NPTS  1024            // 8 curves * 128 steps
// exponent in cell units: (xk - i/512)^2*5000 == (xi - i)^2 * (5000/2^18)
#define INVC_CELL 0.019073486328125f   // 5000 / 262144, exact in fp32
// Dropped terms <= exp(-5000*(36/512)^2) = 1.8e-11 each (validated: rel_err
// bit-identical to dense at BAND=70 and BAND=36).
#define BAND  36.0f

#define STRIPS 32             // i-strips of width TI
#define TI  16                // tile i
#define TJ  16                // tile j
#define BKC 16                // k per staging chunk

// Per-strip compacted point lists (cell coords), built once by k_prep.
__device__ float2 g_spt[STRIPS][NPTS];
__device__ int    g_sn[STRIPS];

// ---------------------------------------------------------------------------
// Kernel A: Bezier evaluation + per-i-strip compaction.
// Block b = strip b (i in [b*16, b*16+15]); accepts xi in strip +- BAND.
// 128 threads, 8 points each, order-preserving (ascending k).
// ---------------------------------------------------------------------------
__global__ __launch_bounds__(128) void k_prep(const float* __restrict__ curves) {
    __shared__ int wsum[4], woff[4];
    const int tid = threadIdx.x, lane = tid & 31, wid = tid >> 5;
    const int strip = blockIdx.x;
    const float ilo = (float)(strip * TI) - BAND;
    const float ihi = (float)(strip * TI + TI - 1) + BAND;

    float xi[8], yi[8];
    bool ok[8];
    int cnt = 0;
    const int kb = tid * 8;                  // 8 consecutive k, same curve
    const int c  = kb >> 7;
    const float* P = curves + c * 8;
    float p0x = __ldg(P+0), p0y = __ldg(P+1), p1x = __ldg(P+2), p1y = __ldg(P+3);
    float p2x = __ldg(P+4), p2y = __ldg(P+5), p3x = __ldg(P+6), p3y = __ldg(P+7);
    #pragma unroll
    for (int u = 0; u < 8; u++) {
        float t = (float)((kb + u) & 127) * (1.0f / 127.0f);
        float a01 = p0x + (p1x - p0x) * t;
        float a12 = p1x + (p2x - p1x) * t;
        float a23 = p2x + (p3x - p2x) * t;
        float qa  = a01 + t * (a12 - a01);
        float qb  = a12 + t * (a23 - a12);
        xi[u] = (qa + t * (qb - qa)) * (float)RES;
        a01 = p0y + (p1y - p0y) * t;
        a12 = p1y + (p2y - p1y) * t;
        a23 = p2y + (p3y - p2y) * t;
        qa  = a01 + t * (a12 - a01);
        qb  = a12 + t * (a23 - a12);
        yi[u] = (qa + t * (qb - qa)) * (float)RES;
        ok[u] = (xi[u] >= ilo) & (xi[u] <= ihi);
        cnt += ok[u] ? 1 : 0;
    }
    int inc = cnt;                           // warp inclusive scan
    #pragma unroll
    for (int d = 1; d < 32; d <<= 1) {
        int n = __shfl_up_sync(0xffffffffu, inc, d);
        if (lane >= d) inc += n;
    }
    if (lane == 31) wsum[wid] = inc;
    __syncthreads();
    if (tid == 0) {
        int s = 0;
        #pragma unroll
        for (int w = 0; w < 4; w++) { woff[w] = s; s += wsum[w]; }
        g_sn[strip] = s;
    }
    __syncthreads();
    int off = woff[wid] + inc - cnt;
    #pragma unroll
    for (int u = 0; u < 8; u++)
        if (ok[u]) g_spt[strip][off++] = make_float2(xi[u], yi[u]);
}

// ---------------------------------------------------------------------------
// Kernel B: one 16x16 tile per block (grid 32x32), 64 threads.
//  1. load this strip's point list into smem
//  2. y-filter + order-preserving compaction (2-warp ballot scan)
//  3. chunks of 16: recompute ex/ey via __expf into smem, rank-1 accumulate
//  4. write tile
// ---------------------------------------------------------------------------
__global__ __launch_bounds__(64) void k_tile(float* __restrict__ out) {
    __shared__ float2 spt[NPTS];             // 8 KB
    __shared__ unsigned short list[NPTS];    // 2 KB
    __shared__ float sex[BKC][TI];           // 1 KB
    __shared__ float sey[BKC][TJ];           // 1 KB
    __shared__ int wsum[2], s_total;

    const int tid = threadIdx.x, lane = tid & 31, wid = tid >> 5;
    const int i0 = blockIdx.x * TI;
    const int j0 = blockIdx.y * TJ;
    const int n = g_sn[blockIdx.x];

    for (int idx = tid; idx < n; idx += 64)
        spt[idx] = g_spt[blockIdx.x][idx];
    if (tid == 0) s_total = 0;
    __syncthreads();

    // ---- y-filter + compaction (ascending order preserved) ----------------
    const float jlo = (float)j0 - BAND, jhi = (float)(j0 + TJ - 1) + BAND;
    for (int base = 0; base < n; base += 64) {
        int k = base + tid;
        bool ok = (k < n) && (spt[k].y >= jlo) && (spt[k].y <= jhi);
        unsigned m = __ballot_sync(0xffffffffu, ok);
        if (lane == 0) wsum[wid] = __popc(m);
        __syncthreads();
        int boff = s_total + (wid ? wsum[0] : 0);
        if (ok) list[boff + __popc(m & ((1u << lane) - 1u))] = (unsigned short)k;
        __syncthreads();
        if (tid == 0) s_total += wsum[0] + wsum[1];
        __syncthreads();
    }
    const int nk = s_total;

    // ---- chunked recompute + rank-1 accumulate ----------------------------
    // staging: 128 slots = 16 rows x 8 groups (4 ex float4 + 4 ey float4);
    // each thread fills 2 slots.
    const int tx = tid & 3;        // 4 i's per thread
    const int ty = tid >> 2;       // 1 j per thread (16)
    float4 acc = make_float4(0.f, 0.f, 0.f, 0.f);

    for (int c = 0; c < nk; c += BKC) {
        float4 v[2];
        int   row_[2], q_[2];
        #pragma unroll
        for (int s2 = 0; s2 < 2; s2++) {
            int s = tid * 2 + s2;
            int row = s >> 3, q = s & 7;
            row_[s2] = row; q_[s2] = q;
            float4 e = make_float4(0.f, 0.f, 0.f, 0.f);
            int r = c + row;
            if (r < nk) {
                float2 p = spt[list[r]];
                float pc, b;
                if (q < 4) { pc = p.x; b = (float)(i0 + q * 4); }
                else       { pc = p.y; b = (float)(j0 + (q - 4) * 4); }
                float d;
                d = pc - (b + 0.f); e.x = __expf(-d * d * INVC_CELL);
                d = pc - (b + 1.f); e.y = __expf(-d * d * INVC_CELL);
                d = pc - (b + 2.f); e.z = __expf(-d * d * INVC_CELL);
                d = pc - (b + 3.f); e.w = __expf(-d * d * INVC_CELL);
            }
            v[s2] = e;
        }
        __syncthreads();                     // prev chunk's compute done
        #pragma unroll
        for (int s2 = 0; s2 < 2; s2++) {
            if (q_[s2] < 4) *(float4*)&sex[row_[s2]][q_[s2] * 4] = v[s2];
            else            *(float4*)&sey[row_[s2]][(q_[s2] - 4) * 4] = v[s2];
        }
        __syncthreads();

        #pragma unroll
        for (int kk = 0; kk < BKC; kk++) {
            float  ey = sey[kk][ty];
            float4 ex = *(const float4*)&sex[kk][tx * 4];
            acc.x += ex.x * ey;
            acc.y += ex.y * ey;
            acc.z += ex.z * ey;
            acc.w += ex.w * ey;
        }
    }

    // ---- write tile (out[j][i], one float4 per thread) --------------------
    *(float4*)&out[(j0 + ty) * RES + i0 + tx * 4] = acc;
}

// ---------------------------------------------------------------------------
extern "C" void kernel_launch(void* const* d_in, const int* in_sizes, int n_in,
                              void* d_out, int out_size) {
    const float* curves = (const float*)d_in[0];
    float* out = (float*)d_out;
    k_prep<<<STRIPS, 128>>>(curves);
    dim3 grid(RES / TI, RES / TJ);
    k_tile<<<grid, 64>>>(out);
}

// round 11
// speedup vs baseline: 1.1550x; 1.1550x over previous
#include <cuda_runtime.h>
#include <cstdint>

#define RES   512
#define NPTS  1024            // 8 curves * 128 steps
// exponent in cell units: (xk - i/512)^2*5000 == (xi - i)^2 * (5000/2^18)
#define INVC_CELL 0.019073486328125f   // 5000 / 262144, exact in fp32
// Dropped terms <= exp(-5000*(36/512)^2) = 1.8e-11 each (validated).
#define BAND  36.0f

#define STRIPS 32             // i-strips of width TI
#define TI  16                // tile i
#define TJ  16                // tile j
#define BKC 32                // k per staging chunk

// packed f32x2 FMA: d = a*b + d
#define FMA_F32X2(d, a, b) \
    asm("fma.rn.f32x2 %0, %1, %2, %0;" : "+l"(d) : "l"(a), "l"(b))
// duplicate one fp32 into both lanes of an f32x2
#define PACK_DUP(out, v) \
    asm("mov.b64 %0, {%1, %1};" : "=l"(out) : "r"(v))

// Per-strip compacted point lists (cell coords) + j-tile occupancy masks.
__device__ float2   g_spt[STRIPS][NPTS];
__device__ int      g_sn[STRIPS];
__device__ unsigned g_mask[STRIPS];

// ---------------------------------------------------------------------------
// Kernel A: Bezier evaluation + per-i-strip compaction + j-tile bitmask.
// ---------------------------------------------------------------------------
__global__ __launch_bounds__(128) void k_prep(const float* __restrict__ curves) {
    __shared__ int wsum[4], woff[4];
    __shared__ unsigned smask;
    const int tid = threadIdx.x, lane = tid & 31, wid = tid >> 5;
    const int strip = blockIdx.x;
    const float ilo = (float)(strip * TI) - BAND;
    const float ihi = (float)(strip * TI + TI - 1) + BAND;
    if (tid == 0) smask = 0u;
    __syncthreads();

    float xi[8], yi[8];
    bool ok[8];
    int cnt = 0;
    unsigned mybits = 0u;
    const int kb = tid * 8;                  // 8 consecutive k, same curve
    const int c  = kb >> 7;
    const float* P = curves + c * 8;
    float p0x = __ldg(P+0), p0y = __ldg(P+1), p1x = __ldg(P+2), p1y = __ldg(P+3);
    float p2x = __ldg(P+4), p2y = __ldg(P+5), p3x = __ldg(P+6), p3y = __ldg(P+7);
    #pragma unroll
    for (int u = 0; u < 8; u++) {
        float t = (float)((kb + u) & 127) * (1.0f / 127.0f);
        float a01 = p0x + (p1x - p0x) * t;
        float a12 = p1x + (p2x - p1x) * t;
        float a23 = p2x + (p3x - p2x) * t;
        float qa  = a01 + t * (a12 - a01);
        float qb  = a12 + t * (a23 - a12);
        xi[u] = (qa + t * (qb - qa)) * (float)RES;
        a01 = p0y + (p1y - p0y) * t;
        a12 = p1y + (p2y - p1y) * t;
        a23 = p2y + (p3y - p2y) * t;
        qa  = a01 + t * (a12 - a01);
        qb  = a12 + t * (a23 - a12);
        yi[u] = (qa + t * (qb - qa)) * (float)RES;
        ok[u] = (xi[u] >= ilo) & (xi[u] <= ihi);
        cnt += ok[u] ? 1 : 0;
        if (ok[u]) {
            // jtile jt is touched iff  jt*16 - BAND <= y <= jt*16 + 15 + BAND
            int jt0 = (int)ceilf((yi[u] - 15.0f - BAND) * (1.0f / 16.0f));
            int jt1 = (int)floorf((yi[u] + BAND) * (1.0f / 16.0f));
            jt0 = jt0 < 0 ? 0 : jt0;
            jt1 = jt1 > 31 ? 31 : jt1;
            if (jt1 >= jt0)
                mybits |= (0xFFFFFFFFu >> (31 - jt1)) & (0xFFFFFFFFu << jt0);
        }
    }
    if (mybits) atomicOr(&smask, mybits);

    int inc = cnt;                           // warp inclusive scan
    #pragma unroll
    for (int d = 1; d < 32; d <<= 1) {
        int n = __shfl_up_sync(0xffffffffu, inc, d);
        if (lane >= d) inc += n;
    }
    if (lane == 31) wsum[wid] = inc;
    __syncthreads();
    if (tid == 0) {
        int s = 0;
        #pragma unroll
        for (int w = 0; w < 4; w++) { woff[w] = s; s += wsum[w]; }
        g_sn[strip] = s;
        g_mask[strip] = smask;
    }
    __syncthreads();
    int off = woff[wid] + inc - cnt;
    #pragma unroll
    for (int u = 0; u < 8; u++)
        if (ok[u]) g_spt[strip][off++] = make_float2(xi[u], yi[u]);
}

// ---------------------------------------------------------------------------
// Kernel B: one 16x16 tile per block (grid 32x32), 64 threads.
//  0. bitmask early-out (empty tiles: zero-write, exit)
//  1. load strip point list (float4 = 2 points per load)
//  2. one-pass order-preserving y-filter (contiguous segments + shfl scan)
//  3. chunks of 32: recompute ex/ey via __expf into smem, FMA2 accumulate
//  4. write tile
// ---------------------------------------------------------------------------
__global__ __launch_bounds__(64) void k_tile(float* __restrict__ out) {
    __shared__ float2 spt[NPTS];             // 8 KB
    __shared__ unsigned short list[NPTS];    // 2 KB
    __shared__ float sex[BKC][TI];           // 2 KB
    __shared__ float sey[BKC][TJ];           // 2 KB
    __shared__ int wsum[2];

    const int tid = threadIdx.x, lane = tid & 31, wid = tid >> 5;
    const int strip = blockIdx.x;
    const int i0 = strip * TI;
    const int j0 = blockIdx.y * TJ;
    const int tx = tid & 3;        // 4 i's per thread (2 f32x2 pairs)
    const int ty = tid >> 2;       // 1 j per thread

    // ---- 0. early-out on empty tiles --------------------------------------
    if (!((g_mask[strip] >> blockIdx.y) & 1u)) {
        *(float4*)&out[(j0 + ty) * RES + i0 + tx * 4] =
            make_float4(0.f, 0.f, 0.f, 0.f);
        return;
    }
    const int n = g_sn[strip];

    // ---- 1. load point list (2 points per float4) -------------------------
    for (int idx = tid; idx < ((n + 1) >> 1); idx += 64)
        *(float4*)&spt[idx * 2] = *(const float4*)&g_spt[strip][idx * 2];
    __syncthreads();

    // ---- 2. one-pass y-filter + order-preserving compaction ---------------
    const float jlo = (float)j0 - BAND, jhi = (float)(j0 + TJ - 1) + BAND;
    const int m  = (n + 63) >> 6;            // contiguous segment per thread
    const int b0 = tid * m;
    const int b1 = (b0 + m < n) ? b0 + m : n;
    int cnt = 0;
    for (int k = b0; k < b1; k++)
        cnt += (spt[k].y >= jlo) & (spt[k].y <= jhi);
    int inc = cnt;
    #pragma unroll
    for (int d = 1; d < 32; d <<= 1) {
        int v = __shfl_up_sync(0xffffffffu, inc, d);
        if (lane >= d) inc += v;
    }
    if (lane == 31) wsum[wid] = inc;
    __syncthreads();
    int off = (inc - cnt) + (wid ? wsum[0] : 0);
    const int nk = wsum[0] + wsum[1];
    for (int k = b0; k < b1; k++)
        if ((spt[k].y >= jlo) & (spt[k].y <= jhi))
            list[off++] = (unsigned short)k;
    __syncthreads();

    // ---- 3. chunked recompute + FMA2 rank-1 accumulate --------------------
    // staging: 256 slots = 32 rows x 8 groups (4 ex + 4 ey float4);
    // thread's 4 slots share one row: even tid -> ex row, odd tid -> ey row.
    const int srow = tid >> 1;               // 0..31
    const bool sey_side = tid & 1;
    unsigned long long acc0 = 0ull, acc1 = 0ull;

    for (int c = 0; c < nk; c += BKC) {
        float4 v[4];
        int r = c + srow;
        if (r < nk) {
            float2 p = spt[list[r]];
            float pc = sey_side ? p.y : p.x;
            float bb = (float)(sey_side ? j0 : i0);
            #pragma unroll
            for (int g = 0; g < 4; g++) {
                float b = bb + (float)(g * 4);
                float d;
                d = pc - (b + 0.f); v[g].x = __expf(-d * d * INVC_CELL);
                d = pc - (b + 1.f); v[g].y = __expf(-d * d * INVC_CELL);
                d = pc - (b + 2.f); v[g].z = __expf(-d * d * INVC_CELL);
                d = pc - (b + 3.f); v[g].w = __expf(-d * d * INVC_CELL);
            }
        } else {
            #pragma unroll
            for (int g = 0; g < 4; g++)
                v[g] = make_float4(0.f, 0.f, 0.f, 0.f);
        }
        __syncthreads();                     // prev chunk's compute done
        #pragma unroll
        for (int g = 0; g < 4; g++) {
            if (sey_side) *(float4*)&sey[srow][g * 4] = v[g];
            else          *(float4*)&sex[srow][g * 4] = v[g];
        }
        __syncthreads();

        #pragma unroll
        for (int kk = 0; kk < BKC; kk++) {
            float eyv = sey[kk][ty];
            unsigned long long eyp;
            PACK_DUP(eyp, __float_as_uint(eyv));
            ulonglong2 exp2 = *(const ulonglong2*)&sex[kk][tx * 4];
            FMA_F32X2(acc0, exp2.x, eyp);
            FMA_F32X2(acc1, exp2.y, eyp);
        }
    }

    // ---- 4. write tile ----------------------------------------------------
    ulonglong2 w; w.x = acc0; w.y = acc1;
    *(ulonglong2*)&out[(j0 + ty) * RES + i0 + tx * 4] = w;
}

// ---------------------------------------------------------------------------
extern "C" void kernel_launch(void* const* d_in, const int* in_sizes, int n_in,
                              void* d_out, int out_size) {
    const float* curves = (const float*)d_in[0];
    float* out = (float*)d_out;
    k_prep<<<STRIPS, 128>>>(curves);
    dim3 grid(STRIPS, RES / TJ);
    k_tile<<<grid, 64>>>(out);
}